// round 2
// baseline (speedup 1.0000x reference)
#include <cuda_runtime.h>
#include <cuda_bf16.h>
#include <cstdint>

// StimulusLayer: dist[b,o] = max_i |x[b,i] - stim[o,i]| (Chebyshev),
// out = state*0.95 + sigmoid((a-dist)*b).  B=128, I=256, O=4096.
//
// R1 design: issue/latency-bound kernel. 3-stage cp.async smem pipeline
// (1 barrier per chunk, loads fully overlap compute), block tile 8b x 64o,
// 64 threads, thread tile 2b x 4o, k staged in KC=32 chunks.

#define B_DIM 128
#define I_DIM 256
#define O_DIM 4096
#define KC     32
#define PITCHF 36                 // 32 + 4 pad floats per row (144B: conflict-free phases)
#define XROWS  8
#define SROWS  64
#define ROWSPB (XROWS + SROWS)    // 72 rows per buffer
#define NCHUNK (I_DIM / KC)       // 8

__device__ __forceinline__ void cp_async16(uint32_t saddr, const void* gptr) {
    asm volatile("cp.async.cg.shared.global [%0], [%1], 16;" :: "r"(saddr), "l"(gptr));
}
__device__ __forceinline__ void cp_commit() {
    asm volatile("cp.async.commit_group;");
}

__global__ __launch_bounds__(64)
void stimulus_kernel(const float* __restrict__ x,
                     const float* __restrict__ stim,
                     const float* __restrict__ a,
                     const float* __restrict__ bvec,
                     const float* __restrict__ state,
                     float* __restrict__ out)
{
    __shared__ float sb[3][ROWSPB * PITCHF];   // 3 x 72 x 36 floats = 31104 B

    const int tid = threadIdx.x;          // 0..63
    const int tb  = tid >> 4;             // 0..3
    const int to  = tid & 15;             // 0..15

    const int b0 = blockIdx.y * 8;
    const int o0 = blockIdx.x * 64;

    const float4* __restrict__ x4 = (const float4*)x;
    const float4* __restrict__ s4 = (const float4*)stim;

    // staging addresses (f4 granularity): x chunk = 8 rows x 8 f4 (1/thread),
    // stim chunk = 64 rows x 8 f4 (8/thread)
    const int srow = tid >> 3;            // 0..7
    const int scol = tid & 7;             // 0..7

    uint32_t sb_base[3];
    #pragma unroll
    for (int i = 0; i < 3; i++)
        sb_base[i] = (uint32_t)__cvta_generic_to_shared(&sb[i][0]);

    auto stage = [&](int kc, int buf) {
        // x: row srow, f4-col scol
        cp_async16(sb_base[buf] + (srow * PITCHF + scol * 4) * 4,
                   &x4[(b0 + srow) * (I_DIM / 4) + kc * (KC / 4) + scol]);
        // stim: 8 f4 per thread
        #pragma unroll
        for (int t = 0; t < 8; t++) {
            int idx = tid + t * 64;       // 0..511
            int row = idx >> 3;           // 0..63
            int col = idx & 7;
            cp_async16(sb_base[buf] + ((XROWS + row) * PITCHF + col * 4) * 4,
                       &s4[(o0 + row) * (I_DIM / 4) + kc * (KC / 4) + col]);
        }
        cp_commit();
    };

    float m[2][4];
    #pragma unroll
    for (int jb = 0; jb < 2; jb++)
        #pragma unroll
        for (int jo = 0; jo < 4; jo++)
            m[jb][jo] = 0.0f;             // |d| >= 0

    stage(0, 0);
    stage(1, 1);

    #pragma unroll
    for (int kc = 0; kc < NCHUNK; kc++) {
        if (kc < NCHUNK - 1) {
            asm volatile("cp.async.wait_group 1;" ::: "memory");
        } else {
            asm volatile("cp.async.wait_group 0;" ::: "memory");
        }
        __syncthreads();                  // chunk kc visible to all threads

        if (kc + 2 < NCHUNK)
            stage(kc + 2, (kc + 2) % 3);  // safe: slot (kc+2)%3 last read in iter kc-1

        const int buf = kc % 3;
        const float* xsb = &sb[buf][0];
        const float* ssb = &sb[buf][XROWS * PITCHF];

        #pragma unroll
        for (int k4 = 0; k4 < KC / 4; k4++) {
            float4 xv[2], sv[4];
            #pragma unroll
            for (int jb = 0; jb < 2; jb++)
                xv[jb] = *(const float4*)&xsb[(tb + 4 * jb) * PITCHF + k4 * 4];
            #pragma unroll
            for (int jo = 0; jo < 4; jo++)
                sv[jo] = *(const float4*)&ssb[(to + 16 * jo) * PITCHF + k4 * 4];

            #pragma unroll
            for (int jb = 0; jb < 2; jb++) {
                #pragma unroll
                for (int jo = 0; jo < 4; jo++) {
                    float mm = m[jb][jo];
                    mm = fmaxf(mm, fabsf(xv[jb].x - sv[jo].x));
                    mm = fmaxf(mm, fabsf(xv[jb].y - sv[jo].y));
                    mm = fmaxf(mm, fabsf(xv[jb].z - sv[jo].z));
                    mm = fmaxf(mm, fabsf(xv[jb].w - sv[jo].w));
                    m[jb][jo] = mm;
                }
            }
        }
    }

    // epilogue: sigmoid((a - dist) * bvec) + decayed state
    #pragma unroll
    for (int jo = 0; jo < 4; jo++) {
        int o = o0 + to + 16 * jo;
        float av = a[o];
        float bv = bvec[o];
        #pragma unroll
        for (int jb = 0; jb < 2; jb++) {
            int b = b0 + tb + 4 * jb;
            float z   = (av - m[jb][jo]) * bv;
            float val = 1.0f / (1.0f + __expf(-z));
            long idx  = (long)b * O_DIM + o;
            out[idx]  = state[idx] * 0.95f + val;
        }
    }
}

extern "C" void kernel_launch(void* const* d_in, const int* in_sizes, int n_in,
                              void* d_out, int out_size)
{
    const float* x     = (const float*)d_in[0];   // (128, 256)
    const float* stim  = (const float*)d_in[1];   // (4096, 256)
    const float* a     = (const float*)d_in[2];   // (4096,)
    const float* bvec  = (const float*)d_in[3];   // (4096,)
    const float* state = (const float*)d_in[4];   // (128, 4096)
    float* out = (float*)d_out;                   // (128, 4096)

    dim3 grid(O_DIM / 64, B_DIM / 8);             // 64 x 16 = 1024 blocks
    stimulus_kernel<<<grid, 64>>>(x, stim, a, bvec, state, out);
}

// round 3
// speedup vs baseline: 1.1117x; 1.1117x over previous
#include <cuda_runtime.h>
#include <cuda_bf16.h>
#include <cstdint>

// StimulusLayer: dist[b,o] = max_i |x[b,i] - stim[o,i]| (Chebyshev),
// out = state*0.95 + sigmoid((a-dist)*b).  B=128, I=256, O=4096.
//
// R2: issue-port-bound. Double warp supply: thread tile 2b x 2o (4 acc),
// 128-thread blocks, block tile 8b x 64o -> 4096 warps (27.7/SM).
// 3-stage cp.async pipeline, KC=32.

#define B_DIM 128
#define I_DIM 256
#define O_DIM 4096
#define KC     32
#define PITCHF 36                 // 32 + 4 pad floats (conflict-free 8-lane phases)
#define XROWS  8
#define SROWS  64
#define ROWSPB (XROWS + SROWS)    // 72 rows/buffer
#define NCHUNK (I_DIM / KC)       // 8

__device__ __forceinline__ void cp_async16(uint32_t saddr, const void* gptr) {
    asm volatile("cp.async.cg.shared.global [%0], [%1], 16;" :: "r"(saddr), "l"(gptr));
}
__device__ __forceinline__ void cp_commit() {
    asm volatile("cp.async.commit_group;");
}

__global__ __launch_bounds__(128)
void stimulus_kernel(const float* __restrict__ x,
                     const float* __restrict__ stim,
                     const float* __restrict__ a,
                     const float* __restrict__ bvec,
                     const float* __restrict__ state,
                     float* __restrict__ out)
{
    __shared__ float sb[3][ROWSPB * PITCHF];   // 31104 B -> 7 blocks/SM

    const int tid = threadIdx.x;          // 0..127
    const int tb  = tid >> 5;             // 0..3  (warp id -> b group; x LDS = broadcast)
    const int to  = tid & 31;             // 0..31 (lane -> o; coalesced stores)

    const int b0 = blockIdx.y * 8;
    const int o0 = blockIdx.x * 64;

    const float4* __restrict__ x4 = (const float4*)x;
    const float4* __restrict__ s4 = (const float4*)stim;

    uint32_t sb_base[3];
    #pragma unroll
    for (int i = 0; i < 3; i++)
        sb_base[i] = (uint32_t)__cvta_generic_to_shared(&sb[i][0]);

    auto stage = [&](int kc, int buf) {
        // x chunk: 8 rows x 8 f4 = 64 f4, threads 0..63
        if (tid < 64) {
            int row = tid >> 3, col = tid & 7;
            cp_async16(sb_base[buf] + (row * PITCHF + col * 4) * 4,
                       &x4[(b0 + row) * (I_DIM / 4) + kc * (KC / 4) + col]);
        }
        // stim chunk: 64 rows x 8 f4 = 512 f4, 4 per thread
        #pragma unroll
        for (int t = 0; t < 4; t++) {
            int idx = tid + t * 128;      // 0..511
            int row = idx >> 3, col = idx & 7;
            cp_async16(sb_base[buf] + ((XROWS + row) * PITCHF + col * 4) * 4,
                       &s4[(o0 + row) * (I_DIM / 4) + kc * (KC / 4) + col]);
        }
        cp_commit();
    };

    float m[2][2];
    #pragma unroll
    for (int jb = 0; jb < 2; jb++)
        #pragma unroll
        for (int jo = 0; jo < 2; jo++)
            m[jb][jo] = 0.0f;             // |d| >= 0

    stage(0, 0);
    stage(1, 1);

    #pragma unroll
    for (int kc = 0; kc < NCHUNK; kc++) {
        if (kc < NCHUNK - 1) {
            asm volatile("cp.async.wait_group 1;" ::: "memory");
        } else {
            asm volatile("cp.async.wait_group 0;" ::: "memory");
        }
        __syncthreads();                  // chunk kc visible

        if (kc + 2 < NCHUNK)
            stage(kc + 2, (kc + 2) % 3);  // slot last read in iter kc-1

        const int buf = kc % 3;
        const float* xsb = &sb[buf][0];
        const float* ssb = &sb[buf][XROWS * PITCHF];

        #pragma unroll
        for (int k4 = 0; k4 < KC / 4; k4++) {
            float4 xv[2], sv[2];
            #pragma unroll
            for (int jb = 0; jb < 2; jb++)          // broadcast reads (same tb per warp)
                xv[jb] = *(const float4*)&xsb[(tb + 4 * jb) * PITCHF + k4 * 4];
            #pragma unroll
            for (int jo = 0; jo < 2; jo++)          // 32 rows, pitch 36 -> conflict-free
                sv[jo] = *(const float4*)&ssb[(to + 32 * jo) * PITCHF + k4 * 4];

            #pragma unroll
            for (int jb = 0; jb < 2; jb++) {
                #pragma unroll
                for (int jo = 0; jo < 2; jo++) {
                    float mm = m[jb][jo];
                    mm = fmaxf(mm, fabsf(xv[jb].x - sv[jo].x));
                    mm = fmaxf(mm, fabsf(xv[jb].y - sv[jo].y));
                    mm = fmaxf(mm, fabsf(xv[jb].z - sv[jo].z));
                    mm = fmaxf(mm, fabsf(xv[jb].w - sv[jo].w));
                    m[jb][jo] = mm;
                }
            }
        }
    }

    // epilogue: sigmoid((a - dist) * bvec) + decayed state
    #pragma unroll
    for (int jo = 0; jo < 2; jo++) {
        int o = o0 + to + 32 * jo;
        float av = a[o];
        float bv = bvec[o];
        #pragma unroll
        for (int jb = 0; jb < 2; jb++) {
            int b = b0 + tb + 4 * jb;
            float z   = (av - m[jb][jo]) * bv;
            float val = 1.0f / (1.0f + __expf(-z));
            long idx  = (long)b * O_DIM + o;
            out[idx]  = state[idx] * 0.95f + val;
        }
    }
}

extern "C" void kernel_launch(void* const* d_in, const int* in_sizes, int n_in,
                              void* d_out, int out_size)
{
    const float* x     = (const float*)d_in[0];   // (128, 256)
    const float* stim  = (const float*)d_in[1];   // (4096, 256)
    const float* a     = (const float*)d_in[2];   // (4096,)
    const float* bvec  = (const float*)d_in[3];   // (4096,)
    const float* state = (const float*)d_in[4];   // (128, 4096)
    float* out = (float*)d_out;                   // (128, 4096)

    dim3 grid(O_DIM / 64, B_DIM / 8);             // 64 x 16 = 1024 blocks, 128 thr
    stimulus_kernel<<<grid, 128>>>(x, stim, a, bvec, state, out);
}